// round 1
// baseline (speedup 1.0000x reference)
#include <cuda_runtime.h>
#include <math.h>
#include <stdint.h>

#define DIMX   1024
#define DI     2048
#define DSTATE 16
#define DTRANK 64
#define BATCH  2
#define LSEQ   2048
#define NTOK   (BATCH*LSEQ)   // 4096

// ---------------- scratch (static device globals; no allocation) ----------------
__device__ float g_u[(size_t)NTOK*DIMX];        // 16.8 MB  layernorm output
__device__ float g_xz[(size_t)NTOK*2*DI];       // 67 MB    in_proj output (xc | z)
__device__ float g_xc[(size_t)NTOK*DI];         // 33.5 MB  conv+silu output
__device__ float g_dbc[(size_t)NTOK*96];        // 1.6 MB   x_proj output (dt|B|C)
__device__ float g_delta[(size_t)NTOK*DI];      // 33.5 MB  softplus(dt_proj)
__device__ float g_y[(size_t)NTOK*DI];          // 33.5 MB  scan output (gated)

// ---------------- layernorm ----------------
__global__ void ln_kernel(const float* __restrict__ x, const float* __restrict__ w,
                          const float* __restrict__ bvec, float* __restrict__ u) {
    int row = blockIdx.x;
    const float4* xr = (const float4*)(x + (size_t)row * DIMX);
    float4 v = xr[threadIdx.x];                 // 256 threads * 4 = 1024
    float s  = v.x + v.y + v.z + v.w;
    float s2 = v.x*v.x + v.y*v.y + v.z*v.z + v.w*v.w;
    __shared__ float sh[2][8];
    #pragma unroll
    for (int o = 16; o; o >>= 1) {
        s  += __shfl_xor_sync(0xffffffffu, s,  o);
        s2 += __shfl_xor_sync(0xffffffffu, s2, o);
    }
    int wi = threadIdx.x >> 5, li = threadIdx.x & 31;
    if (li == 0) { sh[0][wi] = s; sh[1][wi] = s2; }
    __syncthreads();
    if (threadIdx.x < 32) {
        s  = (li < 8) ? sh[0][li] : 0.f;
        s2 = (li < 8) ? sh[1][li] : 0.f;
        #pragma unroll
        for (int o = 4; o; o >>= 1) {
            s  += __shfl_xor_sync(0xffffffffu, s,  o);
            s2 += __shfl_xor_sync(0xffffffffu, s2, o);
        }
        if (li == 0) { sh[0][0] = s; sh[1][0] = s2; }
    }
    __syncthreads();
    float mu  = sh[0][0] * (1.f / DIMX);
    float var = sh[1][0] * (1.f / DIMX) - mu * mu;
    float rs  = rsqrtf(var + 1e-5f);
    float4 wv = ((const float4*)w)[threadIdx.x];
    float4 bv = ((const float4*)bvec)[threadIdx.x];
    float4 o4;
    o4.x = (v.x - mu) * rs * wv.x + bv.x;
    o4.y = (v.y - mu) * rs * wv.y + bv.y;
    o4.z = (v.z - mu) * rs * wv.z + bv.z;
    o4.w = (v.w - mu) * rs * wv.w + bv.w;
    ((float4*)(u + (size_t)row * DIMX))[threadIdx.x] = o4;
}

// ---------------- generic tiled GEMM: C[M,N] = A[M,K] * B[N,K]^T ----------------
// EPI: 0 = none, 1 = +residual E[r*ldc+c], 2 = softplus(acc + E[c])
template<int BM, int BN, int BK, int TM, int TN, int EPI>
__global__ void __launch_bounds__(256)
gemm_tn(const float* __restrict__ A, const float* __restrict__ B, float* __restrict__ C,
        int M, int N, int K, int lda, int ldb, int ldc, const float* __restrict__ E) {
    constexpr int NT = (BM / TM) * (BN / TN);
    static_assert(NT == 256, "thread count");
    __shared__ float As[BK][BM];
    __shared__ float Bs[BK][BN];
    int tid = threadIdx.x;
    int tx = tid % (BN / TN);
    int ty = tid / (BN / TN);
    int rowBase = blockIdx.y * BM;
    int colBase = blockIdx.x * BN;
    float acc[TM][TN];
    #pragma unroll
    for (int i = 0; i < TM; i++)
        #pragma unroll
        for (int j = 0; j < TN; j++) acc[i][j] = 0.f;

    constexpr int KV  = BK / 4;
    constexpr int AF4 = BM * KV;
    constexpr int BF4 = BN * KV;

    for (int kt = 0; kt < K; kt += BK) {
        #pragma unroll
        for (int i = tid; i < AF4; i += NT) {
            int r = i / KV, ks = (i % KV) * 4;
            float4 v = *(const float4*)(A + (size_t)(rowBase + r) * lda + kt + ks);
            As[ks + 0][r] = v.x; As[ks + 1][r] = v.y;
            As[ks + 2][r] = v.z; As[ks + 3][r] = v.w;
        }
        #pragma unroll
        for (int i = tid; i < BF4; i += NT) {
            int r = i / KV, ks = (i % KV) * 4;
            float4 v = make_float4(0.f, 0.f, 0.f, 0.f);
            if (colBase + r < N)
                v = *(const float4*)(B + (size_t)(colBase + r) * ldb + kt + ks);
            Bs[ks + 0][r] = v.x; Bs[ks + 1][r] = v.y;
            Bs[ks + 2][r] = v.z; Bs[ks + 3][r] = v.w;
        }
        __syncthreads();
        #pragma unroll
        for (int k = 0; k < BK; k++) {
            float rA[TM], rB[TN];
            #pragma unroll
            for (int i = 0; i < TM; i++) rA[i] = As[k][ty * TM + i];
            #pragma unroll
            for (int j = 0; j < TN; j++) rB[j] = Bs[k][tx * TN + j];
            #pragma unroll
            for (int i = 0; i < TM; i++)
                #pragma unroll
                for (int j = 0; j < TN; j++)
                    acc[i][j] = fmaf(rA[i], rB[j], acc[i][j]);
        }
        __syncthreads();
    }

    #pragma unroll
    for (int i = 0; i < TM; i++) {
        int r = rowBase + ty * TM + i;
        #pragma unroll
        for (int j = 0; j < TN; j++) {
            int c = colBase + tx * TN + j;
            if (c < N) {
                float v = acc[i][j];
                if (EPI == 1) v += E[(size_t)r * ldc + c];
                if (EPI == 2) { v += E[c]; v = (v > 20.f) ? v : log1pf(__expf(v)); }
                C[(size_t)r * ldc + c] = v;
            }
        }
    }
}

// ---------------- causal depthwise conv (k=4) + bias + SiLU ----------------
__global__ void conv_silu(const float* __restrict__ xz, const float* __restrict__ w,
                          const float* __restrict__ bias, float* __restrict__ xc) {
    int idx = blockIdx.x * blockDim.x + threadIdx.x;   // over NTOK*DI
    if (idx >= NTOK * DI) return;
    int d = idx % DI;
    int t = idx / DI;
    int l = t % LSEQ;
    float4 wv = *(const float4*)(w + (size_t)d * 4);
    const float* base = xz + (size_t)t * (2 * DI) + d;
    float acc = bias[d];
    if (l >= 3) acc = fmaf(wv.x, base[-3 * 2 * DI], acc);
    if (l >= 2) acc = fmaf(wv.y, base[-2 * 2 * DI], acc);
    if (l >= 1) acc = fmaf(wv.z, base[-1 * 2 * DI], acc);
    acc = fmaf(wv.w, base[0], acc);
    xc[idx] = acc / (1.f + __expf(-acc));   // SiLU
}

// ---------------- selective scan ----------------
// 16 lanes per channel (one state per lane), 2 channels per warp, 16 channels/block.
__global__ void __launch_bounds__(256)
scan_kernel(const float* __restrict__ delta, const float* __restrict__ xc,
            const float* __restrict__ dbc, const float* __restrict__ xz,
            const float* __restrict__ A_log, const float* __restrict__ Dv,
            float* __restrict__ y) {
    int b  = blockIdx.x / (DI / 16);
    int c0 = (blockIdx.x % (DI / 16)) * 16;
    int n  = threadIdx.x & 15;          // state index
    int ch = threadIdx.x >> 4;          // channel within block (0..15)
    int d  = c0 + ch;

    float Aval = -__expf(A_log[(size_t)d * DSTATE + n]);
    float Dd   = Dv[d];
    float h = 0.f;

    const float* dp = delta + (size_t)b * LSEQ * DI + d;
    const float* xp = xc    + (size_t)b * LSEQ * DI + d;
    const float* zp = xz    + (size_t)b * LSEQ * (2 * DI) + DI + d;
    const float* bp = dbc   + (size_t)b * LSEQ * 96 + DTRANK + n;        // B
    const float* cp = bp + DSTATE;                                       // C
    float*       yp = y     + (size_t)b * LSEQ * DI + d;

    #pragma unroll 2
    for (int l = 0; l < LSEQ; l++) {
        float dv = *dp;
        float xv = *xp;
        float Bn = *bp;
        float Cn = *cp;
        float dA = __expf(dv * Aval);
        h = fmaf(dA, h, dv * xv * Bn);
        float p = h * Cn;
        p += __shfl_xor_sync(0xffffffffu, p, 8);
        p += __shfl_xor_sync(0xffffffffu, p, 4);
        p += __shfl_xor_sync(0xffffffffu, p, 2);
        p += __shfl_xor_sync(0xffffffffu, p, 1);
        if (n == 0) {
            float zv = *zp;
            float yv = fmaf(xv, Dd, p);
            yv *= zv / (1.f + __expf(-zv));   // * silu(z)
            *yp = yv;
        }
        dp += DI; xp += DI; zp += 2 * DI; bp += 96; cp += 96; yp += DI;
    }
}

// ---------------- launch ----------------
extern "C" void kernel_launch(void* const* d_in, const int* in_sizes, int n_in,
                              void* d_out, int out_size) {
    (void)in_sizes; (void)n_in; (void)out_size;
    const float* x         = (const float*)d_in[0];
    const float* ln_w      = (const float*)d_in[1];
    const float* ln_b      = (const float*)d_in[2];
    const float* in_proj_w = (const float*)d_in[3];
    const float* conv_w    = (const float*)d_in[4];
    const float* conv_b    = (const float*)d_in[5];
    const float* x_proj_w  = (const float*)d_in[6];
    const float* dt_proj_w = (const float*)d_in[7];
    const float* dt_proj_b = (const float*)d_in[8];
    const float* A_log     = (const float*)d_in[9];
    const float* Dv        = (const float*)d_in[10];
    const float* out_proj_w= (const float*)d_in[11];
    float* out = (float*)d_out;

    float *u, *xz, *xc, *dbc, *delta, *yb;
    cudaGetSymbolAddress((void**)&u,     g_u);
    cudaGetSymbolAddress((void**)&xz,    g_xz);
    cudaGetSymbolAddress((void**)&xc,    g_xc);
    cudaGetSymbolAddress((void**)&dbc,   g_dbc);
    cudaGetSymbolAddress((void**)&delta, g_delta);
    cudaGetSymbolAddress((void**)&yb,    g_y);

    // 1) layernorm
    ln_kernel<<<NTOK, 256>>>(x, ln_w, ln_b, u);
    // 2) xz = u @ in_proj_w^T   [4096 x 4096], K=1024
    gemm_tn<128,128,16,8,8,0><<<dim3((2*DI)/128, NTOK/128), 256>>>(
        u, in_proj_w, xz, NTOK, 2*DI, DIMX, DIMX, DIMX, 2*DI, nullptr);
    // 3) causal conv + bias + silu  -> xc
    conv_silu<<<(NTOK*DI)/256, 256>>>(xz, conv_w, conv_b, xc);
    // 4) dbc = xc @ x_proj_w^T   [4096 x 96], K=2048
    gemm_tn<32,128,16,4,4,0><<<dim3(1, NTOK/32), 256>>>(
        xc, x_proj_w, dbc, NTOK, 96, DI, DI, DI, 96, nullptr);
    // 5) delta = softplus(dt @ dt_proj_w^T + b)  [4096 x 2048], K=64 (dt = dbc[:, :64], lda=96)
    gemm_tn<128,128,16,8,8,2><<<dim3(DI/128, NTOK/128), 256>>>(
        dbc, dt_proj_w, delta, NTOK, DI, DTRANK, 96, DTRANK, DI, dt_proj_b);
    // 6) selective scan + D skip + silu(z) gate -> yb
    scan_kernel<<<BATCH*(DI/16), 256>>>(delta, xc, dbc, xz, A_log, Dv, yb);
    // 7) out = x + yb @ out_proj_w^T  [4096 x 1024], K=2048
    gemm_tn<128,128,16,8,8,1><<<dim3(DIMX/128, NTOK/128), 256>>>(
        yb, out_proj_w, out, NTOK, DIMX, DI, DI, DI, DIMX, x);
}

// round 3
// speedup vs baseline: 1.4634x; 1.4634x over previous
#include <cuda_runtime.h>
#include <cuda_bf16.h>
#include <math.h>
#include <stdint.h>

#define DIMX   1024
#define DI     2048
#define DSTATE 16
#define DTRANK 64
#define BATCH  2
#define LSEQ   2048
#define NTOK   (BATCH*LSEQ)   // 4096

// ---------------- scratch (static device globals; no allocation) ----------------
__device__ __nv_bfloat16 g_ub  [(size_t)NTOK*DIMX];     // LN output (bf16)
__device__ __nv_bfloat16 g_win [(size_t)2*DI*DIMX];     // in_proj_w bf16
__device__ float         g_xz  [(size_t)NTOK*2*DI];     // in_proj output (xc | z) fp32
__device__ float         g_xc  [(size_t)NTOK*DI];       // conv+silu fp32 (scan)
__device__ __nv_bfloat16 g_xcb [(size_t)NTOK*DI];       // conv+silu bf16 (x_proj A)
__device__ __nv_bfloat16 g_wx  [(size_t)96*DI];         // x_proj_w bf16
__device__ float         g_dbc [(size_t)NTOK*96];       // x_proj out fp32 (dt|B|C)
__device__ __nv_bfloat16 g_dt  [(size_t)NTOK*DTRANK];   // dt slice bf16
__device__ __nv_bfloat16 g_wdt [(size_t)DI*DTRANK];     // dt_proj_w bf16
__device__ float         g_del [(size_t)NTOK*DI];       // softplus delta fp32
__device__ __nv_bfloat16 g_yb  [(size_t)NTOK*DI];       // scan output bf16 (out_proj A)
__device__ __nv_bfloat16 g_wout[(size_t)DIMX*DI];       // out_proj_w bf16

// ==================== PTX helpers (sm_80-compatible) ====================
__device__ __forceinline__ uint32_t smem_u32(const void* p) {
    uint32_t a;
    asm("{ .reg .u64 t; cvta.to.shared.u64 t, %1; cvt.u32.u64 %0, t; }" : "=r"(a) : "l"(p));
    return a;
}
__device__ __forceinline__ void cpa16(uint32_t s, const void* g, bool pred) {
    int sz = pred ? 16 : 0;
    asm volatile("cp.async.cg.shared.global [%0], [%1], 16, %2;"
                 :: "r"(s), "l"(g), "r"(sz) : "memory");
}
__device__ __forceinline__ void cpa_commit() {
    asm volatile("cp.async.commit_group;" ::: "memory");
}
template<int N>
__device__ __forceinline__ void cpa_wait() {
    asm volatile("cp.async.wait_group %0;" :: "n"(N) : "memory");
}
__device__ __forceinline__ void ldsm4(uint32_t* r, uint32_t addr) {
    asm volatile("ldmatrix.sync.aligned.m8n8.x4.shared.b16 {%0,%1,%2,%3}, [%4];"
                 : "=r"(r[0]), "=r"(r[1]), "=r"(r[2]), "=r"(r[3]) : "r"(addr));
}
__device__ __forceinline__ void mma16816(float* c, const uint32_t* a, const uint32_t* b) {
    asm volatile(
        "mma.sync.aligned.m16n8k16.row.col.f32.bf16.bf16.f32 "
        "{%0,%1,%2,%3}, {%4,%5,%6,%7}, {%8,%9}, {%0,%1,%2,%3};"
        : "+f"(c[0]), "+f"(c[1]), "+f"(c[2]), "+f"(c[3])
        : "r"(a[0]), "r"(a[1]), "r"(a[2]), "r"(a[3]), "r"(b[0]), "r"(b[1]));
}

// ==================== mma.sync GEMM: C[M,N] = A[M,K] @ B[N,K]^T ====================
// Tile 128x128x32. 8 warps (4M x 2N), warp tile 32x64 (2x8 m16n8k16).
// EPI: 0 none, 1 +E[row*ldc+col], 2 softplus(acc + E[col])
#define SSTR 40   // smem row stride in bf16 (32 data + 8 pad)

template<int EPI>
__global__ void __launch_bounds__(256)
gemm_mma(const __nv_bfloat16* __restrict__ A, const __nv_bfloat16* __restrict__ B,
         float* __restrict__ C, int M, int N, int K, int ldc, const float* __restrict__ E)
{
    __shared__ __align__(16) __nv_bfloat16 sA[2][128 * SSTR];
    __shared__ __align__(16) __nv_bfloat16 sB[2][128 * SSTR];

    const int tid  = threadIdx.x;
    const int wid  = tid >> 5;
    const int lane = tid & 31;
    const int warpM = wid >> 1;    // 0..3
    const int warpN = wid & 1;     // 0..1
    const int rowBase = blockIdx.y * 128;
    const int colBase = blockIdx.x * 128;
    const int nK = K >> 5;

    uint32_t aS[2] = { smem_u32(&sA[0][0]), smem_u32(&sA[1][0]) };
    uint32_t bS[2] = { smem_u32(&sB[0][0]), smem_u32(&sB[1][0]) };

    float c[2][8][4];
    #pragma unroll
    for (int mi = 0; mi < 2; mi++)
        #pragma unroll
        for (int ni = 0; ni < 8; ni++)
            #pragma unroll
            for (int j = 0; j < 4; j++) c[mi][ni][j] = 0.f;

    // stage loader: 512 16B-chunks per operand, 2 per thread
    auto load_stage = [&](int kb, int p) {
        const int kt = kb << 5;
        #pragma unroll
        for (int i = 0; i < 2; i++) {
            int ch  = tid + i * 256;
            int row = ch >> 2, cp4 = (ch & 3) * 8;
            cpa16(aS[p] + (row * SSTR + cp4) * 2,
                  A + (size_t)(rowBase + row) * K + kt + cp4, true);
        }
        #pragma unroll
        for (int i = 0; i < 2; i++) {
            int ch  = tid + i * 256;
            int row = ch >> 2, cp4 = (ch & 3) * 8;
            cpa16(bS[p] + (row * SSTR + cp4) * 2,
                  B + (size_t)(colBase + row) * K + kt + cp4, colBase + row < N);
        }
        cpa_commit();
    };

    auto compute = [&](int p) {
        #pragma unroll
        for (int ks = 0; ks < 2; ks++) {
            const int k0 = ks * 16;
            uint32_t a[2][4], b[8][2];
            #pragma unroll
            for (int mi = 0; mi < 2; mi++) {
                int row = warpM * 32 + mi * 16 + (lane & 15);
                int col = k0 + ((lane >> 4) << 3);
                ldsm4(a[mi], aS[p] + (row * SSTR + col) * 2);
            }
            #pragma unroll
            for (int nj = 0; nj < 4; nj++) {
                int r = lane & 7, g = lane >> 3;
                int row = warpN * 64 + nj * 16 + ((g >> 1) << 3) + r;
                int col = k0 + ((g & 1) << 3);
                uint32_t t[4];
                ldsm4(t, bS[p] + (row * SSTR + col) * 2);
                b[2*nj][0]   = t[0]; b[2*nj][1]   = t[1];
                b[2*nj+1][0] = t[2]; b[2*nj+1][1] = t[3];
            }
            #pragma unroll
            for (int mi = 0; mi < 2; mi++)
                #pragma unroll
                for (int ni = 0; ni < 8; ni++)
                    mma16816(c[mi][ni], a[mi], b[ni]);
        }
    };

    load_stage(0, 0);
    for (int kb = 0; kb < nK; kb++) {
        const int p = kb & 1;
        if (kb + 1 < nK) {
            load_stage(kb + 1, p ^ 1);
            cpa_wait<1>();
        } else {
            cpa_wait<0>();
        }
        __syncthreads();
        compute(p);
        __syncthreads();
    }

    // ---- epilogue ----
    #pragma unroll
    for (int mi = 0; mi < 2; mi++) {
        #pragma unroll
        for (int ni = 0; ni < 8; ni++) {
            int row0 = rowBase + warpM * 32 + mi * 16 + (lane >> 2);
            int col0 = colBase + warpN * 64 + ni * 8 + (lane & 3) * 2;
            if (col0 >= N) continue;
            #pragma unroll
            for (int h = 0; h < 2; h++) {
                int row = row0 + h * 8;
                float v0 = c[mi][ni][2*h + 0];
                float v1 = c[mi][ni][2*h + 1];
                if (EPI == 1) {
                    const float2 e = *(const float2*)(E + (size_t)row * ldc + col0);
                    v0 += e.x; v1 += e.y;
                }
                if (EPI == 2) {
                    const float2 e = *(const float2*)(E + col0);
                    v0 += e.x; v1 += e.y;
                    v0 = (v0 > 20.f) ? v0 : log1pf(__expf(v0));
                    v1 = (v1 > 20.f) ? v1 : log1pf(__expf(v1));
                }
                *(float2*)(C + (size_t)row * ldc + col0) = make_float2(v0, v1);
            }
        }
    }
}

// ==================== layernorm (fp32 in, bf16 out) ====================
__global__ void ln_kernel(const float* __restrict__ x, const float* __restrict__ w,
                          const float* __restrict__ bvec, __nv_bfloat16* __restrict__ u) {
    int row = blockIdx.x;
    const float4* xr = (const float4*)(x + (size_t)row * DIMX);
    float4 v = xr[threadIdx.x];
    float s  = v.x + v.y + v.z + v.w;
    float s2 = v.x*v.x + v.y*v.y + v.z*v.z + v.w*v.w;
    __shared__ float sh[2][8];
    #pragma unroll
    for (int o = 16; o; o >>= 1) {
        s  += __shfl_xor_sync(0xffffffffu, s,  o);
        s2 += __shfl_xor_sync(0xffffffffu, s2, o);
    }
    int wi = threadIdx.x >> 5, li = threadIdx.x & 31;
    if (li == 0) { sh[0][wi] = s; sh[1][wi] = s2; }
    __syncthreads();
    if (threadIdx.x < 32) {
        s  = (li < 8) ? sh[0][li] : 0.f;
        s2 = (li < 8) ? sh[1][li] : 0.f;
        #pragma unroll
        for (int o = 4; o; o >>= 1) {
            s  += __shfl_xor_sync(0xffffffffu, s,  o);
            s2 += __shfl_xor_sync(0xffffffffu, s2, o);
        }
        if (li == 0) { sh[0][0] = s; sh[1][0] = s2; }
    }
    __syncthreads();
    float mu  = sh[0][0] * (1.f / DIMX);
    float var = sh[1][0] * (1.f / DIMX) - mu * mu;
    float rs  = rsqrtf(var + 1e-5f);
    float4 wv = ((const float4*)w)[threadIdx.x];
    float4 bv = ((const float4*)bvec)[threadIdx.x];
    float o0 = (v.x - mu) * rs * wv.x + bv.x;
    float o1 = (v.y - mu) * rs * wv.y + bv.y;
    float o2 = (v.z - mu) * rs * wv.z + bv.z;
    float o3 = (v.w - mu) * rs * wv.w + bv.w;
    __nv_bfloat162 p0; p0.x = __float2bfloat16(o0); p0.y = __float2bfloat16(o1);
    __nv_bfloat162 p1; p1.x = __float2bfloat16(o2); p1.y = __float2bfloat16(o3);
    __nv_bfloat162* up = (__nv_bfloat162*)(u + (size_t)row * DIMX + 4 * threadIdx.x);
    up[0] = p0; up[1] = p1;
}

// ==================== converts ====================
__global__ void f2bf(const float* __restrict__ in, __nv_bfloat16* __restrict__ out, int n4) {
    int i = blockIdx.x * blockDim.x + threadIdx.x;
    if (i >= n4) return;
    float4 v = ((const float4*)in)[i];
    __nv_bfloat162 a; a.x = __float2bfloat16(v.x); a.y = __float2bfloat16(v.y);
    __nv_bfloat162 b; b.x = __float2bfloat16(v.z); b.y = __float2bfloat16(v.w);
    ((__nv_bfloat162*)out)[2 * i]     = a;
    ((__nv_bfloat162*)out)[2 * i + 1] = b;
}
__global__ void dtcvt(const float* __restrict__ dbc, __nv_bfloat16* __restrict__ dt) {
    int i = blockIdx.x * blockDim.x + threadIdx.x;   // over NTOK*16
    if (i >= NTOK * 16) return;
    int t = i >> 4, j4 = i & 15;
    float4 v = *(const float4*)(dbc + (size_t)t * 96 + j4 * 4);
    __nv_bfloat162 a; a.x = __float2bfloat16(v.x); a.y = __float2bfloat16(v.y);
    __nv_bfloat162 b; b.x = __float2bfloat16(v.z); b.y = __float2bfloat16(v.w);
    __nv_bfloat162* o = (__nv_bfloat162*)(dt + (size_t)t * 64 + j4 * 4);
    o[0] = a; o[1] = b;
}

// ==================== causal depthwise conv (k=4) + bias + SiLU ====================
__global__ void conv_silu(const float* __restrict__ xz, const float* __restrict__ w,
                          const float* __restrict__ bias, float* __restrict__ xcf,
                          __nv_bfloat16* __restrict__ xcb) {
    int idx = blockIdx.x * blockDim.x + threadIdx.x;   // over NTOK*DI
    if (idx >= NTOK * DI) return;
    int d = idx % DI;
    int t = idx / DI;
    int l = t % LSEQ;
    float4 wv = *(const float4*)(w + (size_t)d * 4);
    const float* base = xz + (size_t)t * (2 * DI) + d;
    float acc = bias[d];
    if (l >= 3) acc = fmaf(wv.x, base[-3 * 2 * DI], acc);
    if (l >= 2) acc = fmaf(wv.y, base[-2 * 2 * DI], acc);
    if (l >= 1) acc = fmaf(wv.z, base[-1 * 2 * DI], acc);
    acc = fmaf(wv.w, base[0], acc);
    float s = acc / (1.f + __expf(-acc));
    xcf[idx] = s;
    xcb[idx] = __float2bfloat16(s);
}

// ==================== selective scan ====================
__global__ void __launch_bounds__(256)
scan_kernel(const float* __restrict__ delta, const float* __restrict__ xc,
            const float* __restrict__ dbc, const float* __restrict__ xz,
            const float* __restrict__ A_log, const float* __restrict__ Dv,
            __nv_bfloat16* __restrict__ y) {
    int b  = blockIdx.x / (DI / 16);
    int c0 = (blockIdx.x % (DI / 16)) * 16;
    int n  = threadIdx.x & 15;
    int ch = threadIdx.x >> 4;
    int d  = c0 + ch;

    float Aval = -__expf(A_log[(size_t)d * DSTATE + n]);
    float Dd   = Dv[d];
    float h = 0.f;

    const float* dp = delta + (size_t)b * LSEQ * DI + d;
    const float* xp = xc    + (size_t)b * LSEQ * DI + d;
    const float* zp = xz    + (size_t)b * LSEQ * (2 * DI) + DI + d;
    const float* bp = dbc   + (size_t)b * LSEQ * 96 + DTRANK + n;
    const float* cp = bp + DSTATE;
    __nv_bfloat16* yp = y   + (size_t)b * LSEQ * DI + d;

    #pragma unroll 2
    for (int l = 0; l < LSEQ; l++) {
        float dv = *dp;
        float xv = *xp;
        float Bn = *bp;
        float Cn = *cp;
        float dA = __expf(dv * Aval);
        h = fmaf(dA, h, dv * xv * Bn);
        float p = h * Cn;
        p += __shfl_xor_sync(0xffffffffu, p, 8);
        p += __shfl_xor_sync(0xffffffffu, p, 4);
        p += __shfl_xor_sync(0xffffffffu, p, 2);
        p += __shfl_xor_sync(0xffffffffu, p, 1);
        if (n == 0) {
            float zv = *zp;
            float yv = fmaf(xv, Dd, p);
            yv *= zv / (1.f + __expf(-zv));
            *yp = __float2bfloat16(yv);
        }
        dp += DI; xp += DI; zp += 2 * DI; bp += 96; cp += 96; yp += DI;
    }
}

// ==================== launch ====================
extern "C" void kernel_launch(void* const* d_in, const int* in_sizes, int n_in,
                              void* d_out, int out_size) {
    (void)in_sizes; (void)n_in; (void)out_size;
    const float* x         = (const float*)d_in[0];
    const float* ln_w      = (const float*)d_in[1];
    const float* ln_b      = (const float*)d_in[2];
    const float* in_proj_w = (const float*)d_in[3];
    const float* conv_w    = (const float*)d_in[4];
    const float* conv_b    = (const float*)d_in[5];
    const float* x_proj_w  = (const float*)d_in[6];
    const float* dt_proj_w = (const float*)d_in[7];
    const float* dt_proj_b = (const float*)d_in[8];
    const float* A_log     = (const float*)d_in[9];
    const float* Dv        = (const float*)d_in[10];
    const float* out_proj_w= (const float*)d_in[11];
    float* out = (float*)d_out;

    __nv_bfloat16 *ub, *win, *xcb, *wx, *dt, *wdt, *yb, *wout;
    float *xz, *xcf, *dbc, *del;
    cudaGetSymbolAddress((void**)&ub,   g_ub);
    cudaGetSymbolAddress((void**)&win,  g_win);
    cudaGetSymbolAddress((void**)&xz,   g_xz);
    cudaGetSymbolAddress((void**)&xcf,  g_xc);
    cudaGetSymbolAddress((void**)&xcb,  g_xcb);
    cudaGetSymbolAddress((void**)&wx,   g_wx);
    cudaGetSymbolAddress((void**)&dbc,  g_dbc);
    cudaGetSymbolAddress((void**)&dt,   g_dt);
    cudaGetSymbolAddress((void**)&wdt,  g_wdt);
    cudaGetSymbolAddress((void**)&del,  g_del);
    cudaGetSymbolAddress((void**)&yb,   g_yb);
    cudaGetSymbolAddress((void**)&wout, g_wout);

    // weight converts (bf16)
    f2bf<<<(2*DI*DIMX/4 + 255)/256, 256>>>(in_proj_w,  win,  2*DI*DIMX/4);
    f2bf<<<(96*DI/4     + 255)/256, 256>>>(x_proj_w,   wx,   96*DI/4);
    f2bf<<<(DI*DTRANK/4 + 255)/256, 256>>>(dt_proj_w,  wdt,  DI*DTRANK/4);
    f2bf<<<(DIMX*DI/4   + 255)/256, 256>>>(out_proj_w, wout, DIMX*DI/4);

    // 1) layernorm -> bf16
    ln_kernel<<<NTOK, 256>>>(x, ln_w, ln_b, ub);
    // 2) xz = u @ in_proj_w^T   [4096 x 4096], K=1024
    gemm_mma<0><<<dim3((2*DI)/128, NTOK/128), 256>>>(
        ub, win, xz, NTOK, 2*DI, DIMX, 2*DI, nullptr);
    // 3) causal conv + bias + silu
    conv_silu<<<(NTOK*DI)/256, 256>>>(xz, conv_w, conv_b, xcf, xcb);
    // 4) dbc = xc @ x_proj_w^T   [4096 x 96], K=2048
    gemm_mma<0><<<dim3(1, NTOK/128), 256>>>(
        xcb, wx, dbc, NTOK, 96, DI, 96, nullptr);
    // 5) dt slice -> bf16
    dtcvt<<<(NTOK*16 + 255)/256, 256>>>(dbc, dt);
    // 6) delta = softplus(dt @ dt_proj_w^T + b)   [4096 x 2048], K=64
    gemm_mma<2><<<dim3(DI/128, NTOK/128), 256>>>(
        dt, wdt, del, NTOK, DI, DTRANK, DI, dt_proj_b);
    // 7) selective scan -> y (bf16)
    scan_kernel<<<BATCH*(DI/16), 256>>>(del, xcf, dbc, xz, A_log, Dv, yb);
    // 8) out = x + y @ out_proj_w^T   [4096 x 1024], K=2048
    gemm_mma<1><<<dim3(DIMX/128, NTOK/128), 256>>>(
        yb, wout, out, NTOK, DIMX, DI, DIMX, x);
}

// round 4
// speedup vs baseline: 1.5197x; 1.0384x over previous
#include <cuda_runtime.h>
#include <cuda_bf16.h>
#include <math.h>
#include <stdint.h>

#define DIMX   1024
#define DI     2048
#define DSTATE 16
#define DTRANK 64
#define BATCH  2
#define LSEQ   2048
#define NTOK   (BATCH*LSEQ)   // 4096

// ---------------- scratch (static device globals; no allocation) ----------------
__device__ __nv_bfloat16 g_ub  [(size_t)NTOK*DIMX];     // LN output (bf16)
__device__ __nv_bfloat16 g_win [(size_t)2*DI*DIMX];     // in_proj_w bf16
__device__ float         g_xz  [(size_t)NTOK*2*DI];     // in_proj output (xc | z) fp32
__device__ float         g_xc  [(size_t)NTOK*DI];       // conv+silu fp32 (scan)
__device__ __nv_bfloat16 g_xcb [(size_t)NTOK*DI];       // conv+silu bf16 (x_proj A)
__device__ __nv_bfloat16 g_wx  [(size_t)96*DI];         // x_proj_w bf16
__device__ float         g_dbc [(size_t)NTOK*96];       // x_proj out fp32 (dt|B|C)
__device__ __nv_bfloat16 g_dt  [(size_t)NTOK*DTRANK];   // dt slice bf16
__device__ __nv_bfloat16 g_wdt [(size_t)DI*DTRANK];     // dt_proj_w bf16
__device__ float         g_del [(size_t)NTOK*DI];       // softplus delta fp32
__device__ __nv_bfloat16 g_yb  [(size_t)NTOK*DI];       // scan output bf16 (out_proj A)
__device__ __nv_bfloat16 g_wout[(size_t)DIMX*DI];       // out_proj_w bf16

// ==================== PTX helpers (sm_80-compatible) ====================
__device__ __forceinline__ uint32_t smem_u32(const void* p) {
    uint32_t a;
    asm("{ .reg .u64 t; cvta.to.shared.u64 t, %1; cvt.u32.u64 %0, t; }" : "=r"(a) : "l"(p));
    return a;
}
__device__ __forceinline__ void cpa16(uint32_t s, const void* g, bool pred) {
    int sz = pred ? 16 : 0;
    asm volatile("cp.async.cg.shared.global [%0], [%1], 16, %2;"
                 :: "r"(s), "l"(g), "r"(sz) : "memory");
}
__device__ __forceinline__ void cpa_commit() {
    asm volatile("cp.async.commit_group;" ::: "memory");
}
template<int N>
__device__ __forceinline__ void cpa_wait() {
    asm volatile("cp.async.wait_group %0;" :: "n"(N) : "memory");
}
__device__ __forceinline__ void ldsm4(uint32_t* r, uint32_t addr) {
    asm volatile("ldmatrix.sync.aligned.m8n8.x4.shared.b16 {%0,%1,%2,%3}, [%4];"
                 : "=r"(r[0]), "=r"(r[1]), "=r"(r[2]), "=r"(r[3]) : "r"(addr));
}
__device__ __forceinline__ void mma16816(float* c, const uint32_t* a, const uint32_t* b) {
    asm volatile(
        "mma.sync.aligned.m16n8k16.row.col.f32.bf16.bf16.f32 "
        "{%0,%1,%2,%3}, {%4,%5,%6,%7}, {%8,%9}, {%0,%1,%2,%3};"
        : "+f"(c[0]), "+f"(c[1]), "+f"(c[2]), "+f"(c[3])
        : "r"(a[0]), "r"(a[1]), "r"(a[2]), "r"(a[3]), "r"(b[0]), "r"(b[1]));
}

// ==================== mma.sync GEMM: C[M,N] = A[M,K] @ B[N,K]^T ====================
// Tile 128x128x64, 3-stage cp.async pipeline, XOR-swizzled smem (128B rows).
// 8 warps (4M x 2N), warp tile 32x64 (2x8 m16n8k16).
// EPI: 0 none, 1 +E[row*ldc+col], 2 softplus(acc + E[col])
#define STAGE_BYTES 32768            // A 16KB + B 16KB per stage
#define GEMM_SMEM   (3 * STAGE_BYTES)

template<int EPI>
__global__ void __launch_bounds__(256, 2)
gemm_mma(const __nv_bfloat16* __restrict__ A, const __nv_bfloat16* __restrict__ B,
         float* __restrict__ C, int M, int N, int K, int ldc, const float* __restrict__ E)
{
    extern __shared__ __align__(16) char smem[];
    const uint32_t sb = smem_u32(smem);

    const int tid  = threadIdx.x;
    const int wid  = tid >> 5;
    const int lane = tid & 31;
    const int warpM = wid >> 1;    // 0..3
    const int warpN = wid & 1;     // 0..1
    const int rowBase = blockIdx.y * 128;
    const int colBase = blockIdx.x * 128;
    const int nK = K >> 6;

    float c[2][8][4];
    #pragma unroll
    for (int mi = 0; mi < 2; mi++)
        #pragma unroll
        for (int ni = 0; ni < 8; ni++)
            #pragma unroll
            for (int j = 0; j < 4; j++) c[mi][ni][j] = 0.f;

    // ---- stage loader: each thread 4 x 16B chunks per operand ----
    auto load_stage = [&](int kb, int s) {
        if (kb < nK) {
            const int kt = kb << 6;
            const uint32_t aB = sb + (uint32_t)s * STAGE_BYTES;
            const uint32_t bB = aB + 16384u;
            #pragma unroll
            for (int i = 0; i < 4; i++) {
                int id  = tid + i * 256;
                int row = id >> 3, ck = id & 7;
                uint32_t sw = (uint32_t)(row * 128 + ((ck ^ (row & 7)) << 4));
                cpa16(aB + sw, A + (size_t)(rowBase + row) * K + kt + ck * 8, true);
            }
            #pragma unroll
            for (int i = 0; i < 4; i++) {
                int id  = tid + i * 256;
                int row = id >> 3, ck = id & 7;
                uint32_t sw = (uint32_t)(row * 128 + ((ck ^ (row & 7)) << 4));
                cpa16(bB + sw, B + (size_t)(colBase + row) * K + kt + ck * 8,
                      colBase + row < N);
            }
        }
        cpa_commit();
    };

    auto compute = [&](int s) {
        const uint32_t aB = sb + (uint32_t)s * STAGE_BYTES;
        const uint32_t bB = aB + 16384u;
        #pragma unroll
        for (int ks = 0; ks < 4; ks++) {
            uint32_t a[2][4], b[8][2];
            #pragma unroll
            for (int mi = 0; mi < 2; mi++) {
                int row = warpM * 32 + mi * 16 + (lane & 15);
                int ck  = ks * 2 + (lane >> 4);
                ldsm4(a[mi], aB + row * 128 + ((ck ^ (row & 7)) << 4));
            }
            #pragma unroll
            for (int nj = 0; nj < 4; nj++) {
                int r = lane & 7, g = lane >> 3;
                int row = warpN * 64 + nj * 16 + ((g >> 1) << 3) + r;
                int ck  = ks * 2 + (g & 1);
                uint32_t t[4];
                ldsm4(t, bB + row * 128 + ((ck ^ (row & 7)) << 4));
                b[2*nj][0]   = t[0]; b[2*nj][1]   = t[1];
                b[2*nj+1][0] = t[2]; b[2*nj+1][1] = t[3];
            }
            #pragma unroll
            for (int mi = 0; mi < 2; mi++)
                #pragma unroll
                for (int ni = 0; ni < 8; ni++)
                    mma16816(c[mi][ni], a[mi], b[ni]);
        }
    };

    // ---- 3-stage pipeline: one __syncthreads per K-step ----
    load_stage(0, 0);
    load_stage(1, 1);
    int s2 = 2;
    for (int kb = 0; kb < nK; kb++) {
        cpa_wait<1>();
        __syncthreads();
        load_stage(kb + 2, s2);
        s2 = (s2 == 2) ? 0 : s2 + 1;
        compute((kb == 0) ? 0 : ((kb % 3 == 0) ? 0 : kb % 3));
    }

    // ---- epilogue ----
    #pragma unroll
    for (int mi = 0; mi < 2; mi++) {
        #pragma unroll
        for (int ni = 0; ni < 8; ni++) {
            int row0 = rowBase + warpM * 32 + mi * 16 + (lane >> 2);
            int col0 = colBase + warpN * 64 + ni * 8 + (lane & 3) * 2;
            if (col0 >= N) continue;
            #pragma unroll
            for (int h = 0; h < 2; h++) {
                int row = row0 + h * 8;
                float v0 = c[mi][ni][2*h + 0];
                float v1 = c[mi][ni][2*h + 1];
                if (EPI == 1) {
                    const float2 e = *(const float2*)(E + (size_t)row * ldc + col0);
                    v0 += e.x; v1 += e.y;
                }
                if (EPI == 2) {
                    const float2 e = *(const float2*)(E + col0);
                    v0 += e.x; v1 += e.y;
                    v0 = (v0 > 20.f) ? v0 : log1pf(__expf(v0));
                    v1 = (v1 > 20.f) ? v1 : log1pf(__expf(v1));
                }
                *(float2*)(C + (size_t)row * ldc + col0) = make_float2(v0, v1);
            }
        }
    }
}

// ==================== layernorm (fp32 in, bf16 out) ====================
__global__ void ln_kernel(const float* __restrict__ x, const float* __restrict__ w,
                          const float* __restrict__ bvec, __nv_bfloat16* __restrict__ u) {
    int row = blockIdx.x;
    const float4* xr = (const float4*)(x + (size_t)row * DIMX);
    float4 v = xr[threadIdx.x];
    float s  = v.x + v.y + v.z + v.w;
    float s2 = v.x*v.x + v.y*v.y + v.z*v.z + v.w*v.w;
    __shared__ float sh[2][8];
    #pragma unroll
    for (int o = 16; o; o >>= 1) {
        s  += __shfl_xor_sync(0xffffffffu, s,  o);
        s2 += __shfl_xor_sync(0xffffffffu, s2, o);
    }
    int wi = threadIdx.x >> 5, li = threadIdx.x & 31;
    if (li == 0) { sh[0][wi] = s; sh[1][wi] = s2; }
    __syncthreads();
    if (threadIdx.x < 32) {
        s  = (li < 8) ? sh[0][li] : 0.f;
        s2 = (li < 8) ? sh[1][li] : 0.f;
        #pragma unroll
        for (int o = 4; o; o >>= 1) {
            s  += __shfl_xor_sync(0xffffffffu, s,  o);
            s2 += __shfl_xor_sync(0xffffffffu, s2, o);
        }
        if (li == 0) { sh[0][0] = s; sh[1][0] = s2; }
    }
    __syncthreads();
    float mu  = sh[0][0] * (1.f / DIMX);
    float var = sh[1][0] * (1.f / DIMX) - mu * mu;
    float rs  = rsqrtf(var + 1e-5f);
    float4 wv = ((const float4*)w)[threadIdx.x];
    float4 bv = ((const float4*)bvec)[threadIdx.x];
    float o0 = (v.x - mu) * rs * wv.x + bv.x;
    float o1 = (v.y - mu) * rs * wv.y + bv.y;
    float o2 = (v.z - mu) * rs * wv.z + bv.z;
    float o3 = (v.w - mu) * rs * wv.w + bv.w;
    __nv_bfloat162 p0; p0.x = __float2bfloat16(o0); p0.y = __float2bfloat16(o1);
    __nv_bfloat162 p1; p1.x = __float2bfloat16(o2); p1.y = __float2bfloat16(o3);
    __nv_bfloat162* up = (__nv_bfloat162*)(u + (size_t)row * DIMX + 4 * threadIdx.x);
    up[0] = p0; up[1] = p1;
}

// ==================== converts ====================
__global__ void f2bf(const float* __restrict__ in, __nv_bfloat16* __restrict__ out, int n4) {
    int i = blockIdx.x * blockDim.x + threadIdx.x;
    if (i >= n4) return;
    float4 v = ((const float4*)in)[i];
    __nv_bfloat162 a; a.x = __float2bfloat16(v.x); a.y = __float2bfloat16(v.y);
    __nv_bfloat162 b; b.x = __float2bfloat16(v.z); b.y = __float2bfloat16(v.w);
    ((__nv_bfloat162*)out)[2 * i]     = a;
    ((__nv_bfloat162*)out)[2 * i + 1] = b;
}
__global__ void dtcvt(const float* __restrict__ dbc, __nv_bfloat16* __restrict__ dt) {
    int i = blockIdx.x * blockDim.x + threadIdx.x;   // over NTOK*16
    if (i >= NTOK * 16) return;
    int t = i >> 4, j4 = i & 15;
    float4 v = *(const float4*)(dbc + (size_t)t * 96 + j4 * 4);
    __nv_bfloat162 a; a.x = __float2bfloat16(v.x); a.y = __float2bfloat16(v.y);
    __nv_bfloat162 b; b.x = __float2bfloat16(v.z); b.y = __float2bfloat16(v.w);
    __nv_bfloat162* o = (__nv_bfloat162*)(dt + (size_t)t * 64 + j4 * 4);
    o[0] = a; o[1] = b;
}

// ==================== causal depthwise conv (k=4) + bias + SiLU ====================
__global__ void conv_silu(const float* __restrict__ xz, const float* __restrict__ w,
                          const float* __restrict__ bias, float* __restrict__ xcf,
                          __nv_bfloat16* __restrict__ xcb) {
    int idx = blockIdx.x * blockDim.x + threadIdx.x;   // over NTOK*DI
    if (idx >= NTOK * DI) return;
    int d = idx % DI;
    int t = idx / DI;
    int l = t % LSEQ;
    float4 wv = *(const float4*)(w + (size_t)d * 4);
    const float* base = xz + (size_t)t * (2 * DI) + d;
    float acc = bias[d];
    if (l >= 3) acc = fmaf(wv.x, base[-3 * 2 * DI], acc);
    if (l >= 2) acc = fmaf(wv.y, base[-2 * 2 * DI], acc);
    if (l >= 1) acc = fmaf(wv.z, base[-1 * 2 * DI], acc);
    acc = fmaf(wv.w, base[0], acc);
    float s = acc / (1.f + __expf(-acc));
    xcf[idx] = s;
    xcb[idx] = __float2bfloat16(s);
}

// ==================== selective scan ====================
__global__ void __launch_bounds__(256)
scan_kernel(const float* __restrict__ delta, const float* __restrict__ xc,
            const float* __restrict__ dbc, const float* __restrict__ xz,
            const float* __restrict__ A_log, const float* __restrict__ Dv,
            __nv_bfloat16* __restrict__ y) {
    int b  = blockIdx.x / (DI / 16);
    int c0 = (blockIdx.x % (DI / 16)) * 16;
    int n  = threadIdx.x & 15;
    int ch = threadIdx.x >> 4;
    int d  = c0 + ch;

    float Aval = -__expf(A_log[(size_t)d * DSTATE + n]);
    float Dd   = Dv[d];
    float h = 0.f;

    const float* dp = delta + (size_t)b * LSEQ * DI + d;
    const float* xp = xc    + (size_t)b * LSEQ * DI + d;
    const float* zp = xz    + (size_t)b * LSEQ * (2 * DI) + DI + d;
    const float* bp = dbc   + (size_t)b * LSEQ * 96 + DTRANK + n;
    const float* cp = bp + DSTATE;
    __nv_bfloat16* yp = y   + (size_t)b * LSEQ * DI + d;

    #pragma unroll 2
    for (int l = 0; l < LSEQ; l++) {
        float dv = *dp;
        float xv = *xp;
        float Bn = *bp;
        float Cn = *cp;
        float dA = __expf(dv * Aval);
        h = fmaf(dA, h, dv * xv * Bn);
        float p = h * Cn;
        p += __shfl_xor_sync(0xffffffffu, p, 8);
        p += __shfl_xor_sync(0xffffffffu, p, 4);
        p += __shfl_xor_sync(0xffffffffu, p, 2);
        p += __shfl_xor_sync(0xffffffffu, p, 1);
        if (n == 0) {
            float zv = *zp;
            float yv = fmaf(xv, Dd, p);
            yv *= zv / (1.f + __expf(-zv));
            *yp = __float2bfloat16(yv);
        }
        dp += DI; xp += DI; zp += 2 * DI; bp += 96; cp += 96; yp += DI;
    }
}

// ==================== launch ====================
extern "C" void kernel_launch(void* const* d_in, const int* in_sizes, int n_in,
                              void* d_out, int out_size) {
    (void)in_sizes; (void)n_in; (void)out_size;
    const float* x         = (const float*)d_in[0];
    const float* ln_w      = (const float*)d_in[1];
    const float* ln_b      = (const float*)d_in[2];
    const float* in_proj_w = (const float*)d_in[3];
    const float* conv_w    = (const float*)d_in[4];
    const float* conv_b    = (const float*)d_in[5];
    const float* x_proj_w  = (const float*)d_in[6];
    const float* dt_proj_w = (const float*)d_in[7];
    const float* dt_proj_b = (const float*)d_in[8];
    const float* A_log     = (const float*)d_in[9];
    const float* Dv        = (const float*)d_in[10];
    const float* out_proj_w= (const float*)d_in[11];
    float* out = (float*)d_out;

    __nv_bfloat16 *ub, *win, *xcb, *wx, *dt, *wdt, *yb, *wout;
    float *xz, *xcf, *dbc, *del;
    cudaGetSymbolAddress((void**)&ub,   g_ub);
    cudaGetSymbolAddress((void**)&win,  g_win);
    cudaGetSymbolAddress((void**)&xz,   g_xz);
    cudaGetSymbolAddress((void**)&xcf,  g_xc);
    cudaGetSymbolAddress((void**)&xcb,  g_xcb);
    cudaGetSymbolAddress((void**)&wx,   g_wx);
    cudaGetSymbolAddress((void**)&dbc,  g_dbc);
    cudaGetSymbolAddress((void**)&dt,   g_dt);
    cudaGetSymbolAddress((void**)&wdt,  g_wdt);
    cudaGetSymbolAddress((void**)&del,  g_del);
    cudaGetSymbolAddress((void**)&yb,   g_yb);
    cudaGetSymbolAddress((void**)&wout, g_wout);

    cudaFuncSetAttribute(gemm_mma<0>, cudaFuncAttributeMaxDynamicSharedMemorySize, GEMM_SMEM);
    cudaFuncSetAttribute(gemm_mma<1>, cudaFuncAttributeMaxDynamicSharedMemorySize, GEMM_SMEM);
    cudaFuncSetAttribute(gemm_mma<2>, cudaFuncAttributeMaxDynamicSharedMemorySize, GEMM_SMEM);

    // weight converts (bf16)
    f2bf<<<(2*DI*DIMX/4 + 255)/256, 256>>>(in_proj_w,  win,  2*DI*DIMX/4);
    f2bf<<<(96*DI/4     + 255)/256, 256>>>(x_proj_w,   wx,   96*DI/4);
    f2bf<<<(DI*DTRANK/4 + 255)/256, 256>>>(dt_proj_w,  wdt,  DI*DTRANK/4);
    f2bf<<<(DIMX*DI/4   + 255)/256, 256>>>(out_proj_w, wout, DIMX*DI/4);

    // 1) layernorm -> bf16
    ln_kernel<<<NTOK, 256>>>(x, ln_w, ln_b, ub);
    // 2) xz = u @ in_proj_w^T   [4096 x 4096], K=1024
    gemm_mma<0><<<dim3((2*DI)/128, NTOK/128), 256, GEMM_SMEM>>>(
        ub, win, xz, NTOK, 2*DI, DIMX, 2*DI, nullptr);
    // 3) causal conv + bias + silu
    conv_silu<<<(NTOK*DI)/256, 256>>>(xz, conv_w, conv_b, xcf, xcb);
    // 4) dbc = xc @ x_proj_w^T   [4096 x 96], K=2048
    gemm_mma<0><<<dim3(1, NTOK/128), 256, GEMM_SMEM>>>(
        xcb, wx, dbc, NTOK, 96, DI, 96, nullptr);
    // 5) dt slice -> bf16
    dtcvt<<<(NTOK*16 + 255)/256, 256>>>(dbc, dt);
    // 6) delta = softplus(dt @ dt_proj_w^T + b)   [4096 x 2048], K=64
    gemm_mma<2><<<dim3(DI/128, NTOK/128), 256, GEMM_SMEM>>>(
        dt, wdt, del, NTOK, DI, DTRANK, DI, dt_proj_b);
    // 7) selective scan -> y (bf16)
    scan_kernel<<<BATCH*(DI/16), 256>>>(del, xcf, dbc, xz, A_log, Dv, yb);
    // 8) out = x + y @ out_proj_w^T   [4096 x 1024], K=2048
    gemm_mma<1><<<dim3(DIMX/128, NTOK/128), 256, GEMM_SMEM>>>(
        yb, wout, out, NTOK, DIMX, DI, DIMX, x);
}